// round 16
// baseline (speedup 1.0000x reference)
#include <cuda_runtime.h>
#include <cuda_fp16.h>
#include <cstdint>
#include <cstddef>

namespace {
constexpr int Bn   = 1024;
constexpr int BnP  = 1032;   // padded rows (zero tail)
constexpr int Tn   = 512;
constexpr int Hn   = 64;
constexpr int NB   = 7;      // real rows per block -> grid 147 (N=8 with pad row)
constexpr int GRID = 147;
constexpr int NT   = 512;    // 16 warps
constexpr int RQ   = 108;    // bq row stride in uint4 (mod 8 = 4 -> conflict-free)
// uint4 slot bases within a row:
//   L0: x triple-buffer @ 0,8,16 ; h parity @ 24(+8)
//   L1: x parity @ 40(+8) ; h parity @ 56(+8)
//   L2: x parity @ 72(+8) ; h parity @ 88(+8)
}

// Layer-0 input transposed+padded: [t][b][64] (cols 22..63 zero)
__device__ float g_x64[(size_t)Tn * BnP * 64];

__device__ __forceinline__ float htanh(float x) {   // HW MUFU.TANH
    float y;
    asm("tanh.approx.f32 %0, %1;" : "=f"(y) : "f"(x));
    return y;
}
__device__ __forceinline__ float sigm(float x) {    // 0.5 + 0.5*tanh(x/2)
    return fmaf(htanh(0.5f * x), 0.5f, 0.5f);
}
__device__ __forceinline__ uint32_t h2pk(float a, float b) {   // fp16x2 pack
    __half2 t = __floats2half2_rn(a, b);
    return *reinterpret_cast<uint32_t*>(&t);
}

// m16n8k16 fp16 MMA, fp32 accumulate (sm_80 baseline PTX).
__device__ __forceinline__ void hmma(float& d0, float& d1, float& d2, float& d3,
                                     uint32_t a0, uint32_t a1, uint32_t a2, uint32_t a3,
                                     uint32_t b0, uint32_t b1) {
    asm volatile(
        "mma.sync.aligned.m16n8k16.row.col.f32.f16.f16.f32 "
        "{%0,%1,%2,%3}, {%4,%5,%6,%7}, {%8,%9}, {%0,%1,%2,%3};"
        : "+f"(d0), "+f"(d1), "+f"(d2), "+f"(d3)
        : "r"(a0), "r"(a1), "r"(a2), "r"(a3), "r"(b0), "r"(b1));
}

// Transpose x[b][22][t] -> g_x64[t][b][0..63] (cols 22..63 zero).
__global__ void __launch_bounds__(256)
transpose_x_k(const float* __restrict__ x)
{
    const int b  = blockIdx.x >> 3;
    const int t0 = (blockIdx.x & 7) * 64;
    __shared__ float tile[22][65];
    for (int e = threadIdx.x; e < 22 * 64; e += 256) {
        int i = e / 64, tt = e - i * 64;
        tile[i][tt] = x[(size_t)b * (22 * Tn) + i * Tn + t0 + tt];
    }
    __syncthreads();
    for (int e = threadIdx.x; e < 64 * 64; e += 256) {
        int tt = e >> 6, i = e & 63;
        g_x64[((size_t)(t0 + tt) * BnP + b) * 64 + i] = (i < 22) ? tile[i][tt] : 0.f;
    }
}

// Fully-fused 3-layer pipelined LSTM. At step s: L0 does t=s, L1 t=s-1, L2 t=s-2.
// Inter-layer h flows through the smem fragment tile (no global traffic).
// pure-fp16 HMMA, warp-local row-split combine, ONE __syncthreads per step.
// Warp w's m16 A-tile rows (gathered, permuted), identical for all layers:
//   gid 0..7: gate (gid>>2 ? f : i), cell 4w+(gid&3); gid+8: (o : g) same cell.
__global__ void __launch_bounds__(NT, 1)
lstm3_k(const float* __restrict__ wih0, const float* __restrict__ whh0,
        const float* __restrict__ bih0, const float* __restrict__ bhh0,
        const float* __restrict__ wih1, const float* __restrict__ whh1,
        const float* __restrict__ bih1, const float* __restrict__ bhh1,
        const float* __restrict__ wih2, const float* __restrict__ whh2,
        const float* __restrict__ bih2, const float* __restrict__ bhh2,
        const float* __restrict__ w_fc, const float* __restrict__ b_fc,
        float* __restrict__ out_fc)
{
    __shared__ __align__(16) uint4 bq[8][RQ];   // fp16 fragment tile
    __shared__ float h_s[8][64];                // final h of L2 for FC

    const int tid  = threadIdx.x;
    const int lane = tid & 31;
    const int wrp  = tid >> 5;
    const int gid  = lane >> 2;
    const int qid  = lane & 3;
    const int b0   = blockIdx.x * NB;
    const int nrows = (Bn - b0 < NB) ? (Bn - b0) : NB;

    // permuted weight rows
    const int cell = 4 * wrp + (gid & 3);
    const int m0 = ((gid >> 2) ? 64 : 0)    + cell;   // i or f row
    const int m1 = ((gid >> 2) ? 192 : 128) + cell;   // g or o row

    // ---- fp16 weight fragments, registers (3 layers) ----
    uint32_t ax0[2][4], ah0[4][4];
    uint32_t ax1[4][4], ah1[4][4];
    uint32_t ax2[4][4], ah2[4][4];
    {
        auto wx0 = [&](int m, int k) -> float {
            return (k < 22) ? wih0[m * 22 + k] : 0.f;
        };
#pragma unroll
        for (int kc = 0; kc < 2; kc++) {
            const int k0 = kc * 16 + qid * 2, k1 = k0 + 8;
            ax0[kc][0] = h2pk(wx0(m0, k0), wx0(m0, k0 + 1));
            ax0[kc][1] = h2pk(wx0(m1, k0), wx0(m1, k0 + 1));
            ax0[kc][2] = h2pk(wx0(m0, k1), wx0(m0, k1 + 1));
            ax0[kc][3] = h2pk(wx0(m1, k1), wx0(m1, k1 + 1));
        }
#pragma unroll
        for (int kc = 0; kc < 4; kc++) {
            const int k0 = kc * 16 + qid * 2, k1 = k0 + 8;
            ah0[kc][0] = h2pk(whh0[m0 * 64 + k0], whh0[m0 * 64 + k0 + 1]);
            ah0[kc][1] = h2pk(whh0[m1 * 64 + k0], whh0[m1 * 64 + k0 + 1]);
            ah0[kc][2] = h2pk(whh0[m0 * 64 + k1], whh0[m0 * 64 + k1 + 1]);
            ah0[kc][3] = h2pk(whh0[m1 * 64 + k1], whh0[m1 * 64 + k1 + 1]);
            ax1[kc][0] = h2pk(wih1[m0 * 64 + k0], wih1[m0 * 64 + k0 + 1]);
            ax1[kc][1] = h2pk(wih1[m1 * 64 + k0], wih1[m1 * 64 + k0 + 1]);
            ax1[kc][2] = h2pk(wih1[m0 * 64 + k1], wih1[m0 * 64 + k1 + 1]);
            ax1[kc][3] = h2pk(wih1[m1 * 64 + k1], wih1[m1 * 64 + k1 + 1]);
            ah1[kc][0] = h2pk(whh1[m0 * 64 + k0], whh1[m0 * 64 + k0 + 1]);
            ah1[kc][1] = h2pk(whh1[m1 * 64 + k0], whh1[m1 * 64 + k0 + 1]);
            ah1[kc][2] = h2pk(whh1[m0 * 64 + k1], whh1[m0 * 64 + k1 + 1]);
            ah1[kc][3] = h2pk(whh1[m1 * 64 + k1], whh1[m1 * 64 + k1 + 1]);
            ax2[kc][0] = h2pk(wih2[m0 * 64 + k0], wih2[m0 * 64 + k0 + 1]);
            ax2[kc][1] = h2pk(wih2[m1 * 64 + k0], wih2[m1 * 64 + k0 + 1]);
            ax2[kc][2] = h2pk(wih2[m0 * 64 + k1], wih2[m0 * 64 + k1 + 1]);
            ax2[kc][3] = h2pk(wih2[m1 * 64 + k1], wih2[m1 * 64 + k1 + 1]);
            ah2[kc][0] = h2pk(whh2[m0 * 64 + k0], whh2[m0 * 64 + k0 + 1]);
            ah2[kc][1] = h2pk(whh2[m1 * 64 + k0], whh2[m1 * 64 + k0 + 1]);
            ah2[kc][2] = h2pk(whh2[m0 * 64 + k1], whh2[m0 * 64 + k1 + 1]);
            ah2[kc][3] = h2pk(whh2[m1 * 64 + k1], whh2[m1 * 64 + k1 + 1]);
        }
    }
    const float bA0 = bih0[m0] + bhh0[m0], bB0 = bih0[m1] + bhh0[m1];
    const float bA1 = bih1[m0] + bhh1[m0], bB1 = bih1[m1] + bhh1[m1];
    const float bA2 = bih2[m0] + bhh2[m0], bB2 = bih2[m1] + bhh2[m1];

    // combine identities (row-split)
    const bool sideA = (lane < 16);
    const int  myrow = 2 * qid + (sideA ? 0 : 1);
    float cst0 = 0.f, cst1 = 0.f, cst2 = 0.f;

    // staging identity (coalesced)
    const int sr = tid >> 6, sc = tid & 63;
    const int xw_u4   = (sc >> 5) * 4 + ((sc >> 1) & 3);
    const int xw_comp = (((sc >> 4) & 1) * 2 + ((sc >> 3) & 1)) * 2 + (sc & 1);
    const int hw_u4   = (cell >> 5) * 4 + ((cell >> 1) & 3);
    const int hw_comp = (((cell >> 4) & 1) * 2 + ((cell >> 3) & 1)) * 2 + (cell & 1);

    auto putx = [&](int S, float v) {   // L0 x staging (k-index sc)
        reinterpret_cast<__half*>(&bq[sr][S + xw_u4])[xw_comp] = __float2half_rn(v);
    };
    auto puth = [&](int row, int S, float v) {   // combine h write (k-index cell)
        reinterpret_cast<__half*>(&bq[row][S + hw_u4])[hw_comp] = __float2half_rn(v);
    };
    auto ldx = [&](int t) -> float {
        return (t < Tn) ? g_x64[((size_t)t * BnP + b0 + sr) * 64 + sc] : 0.f;
    };
    // warp-local row-split combine: returns h for (cell, myrow)
    auto combine = [&](float d0, float d1, float d2, float d3, float& cst) -> float {
        const float s1 = __shfl_xor_sync(0xffffffffu, sideA ? d1 : d0, 16);
        const float s2 = __shfl_xor_sync(0xffffffffu, sideA ? d3 : d2, 16);
        const float gi = sideA ? d0 : s1;
        const float gf = sideA ? s1 : d1;
        const float gg = sideA ? d2 : s2;
        const float go = sideA ? s2 : d3;
        const float iv = sigm(gi), fv = sigm(gf), gv = htanh(gg), ov = sigm(go);
        cst = fv * cst + iv * gv;
        return ov * htanh(cst);
    };

    // ---- zero fragment tile (h(-1)=0, unused slots 0) ----
    for (int e = tid; e < 8 * RQ * 4; e += NT)
        reinterpret_cast<uint32_t*>(&bq[0][0])[e] = 0u;
    __syncthreads();
    // L0 x triple-buffer: x(0)->slot0, x(1)->slot1 (slot index = t mod 3)
    putx(0, ldx(0));
    putx(8, ldx(1));
    __syncthreads();

    const uint4* myrowq = &bq[gid][qid];

    // deep x prefetch: xna = x(s+2), xnb = x(s+3)
    float xna = ldx(2);
    float xnb = ldx(3);
    int xsl_w = 2;   // (s+2) mod 3 at s=0

    for (int s = 0; s < Tn + 2; s++) {
        __syncthreads();   // ONE barrier: all parity/3-buffer slots settled

        // LDG x(s+4) immediately (consumed 2 steps from now)
        float xnew = 0.f;
        if (s + 4 < Tn)
            xnew = g_x64[((size_t)(s + 4) * BnP + b0 + sr) * 64 + sc];

        // ================= Layer 0: t = s =================
        if (s < Tn) {
            const int t = s;
            const int xS = 8 * (t - (t / 3) * 3);      // t mod 3
            const int hS = 24 + 8 * ((t + 1) & 1);
            const uint4 xa = myrowq[xS];
            const uint4 ha = myrowq[hS], hb = myrowq[hS + 4];
            float d0 = bA0, d1 = bA0, d2 = bB0, d3 = bB0;
            float p0 = 0.f, p1 = 0.f, p2 = 0.f, p3 = 0.f;
            hmma(d0, d1, d2, d3, ax0[0][0], ax0[0][1], ax0[0][2], ax0[0][3], xa.x, xa.y);
            hmma(p0, p1, p2, p3, ax0[1][0], ax0[1][1], ax0[1][2], ax0[1][3], xa.z, xa.w);
            hmma(d0, d1, d2, d3, ah0[0][0], ah0[0][1], ah0[0][2], ah0[0][3], ha.x, ha.y);
            hmma(p0, p1, p2, p3, ah0[2][0], ah0[2][1], ah0[2][2], ah0[2][3], hb.x, hb.y);
            hmma(d0, d1, d2, d3, ah0[1][0], ah0[1][1], ah0[1][2], ah0[1][3], ha.z, ha.w);
            hmma(p0, p1, p2, p3, ah0[3][0], ah0[3][1], ah0[3][2], ah0[3][3], hb.z, hb.w);
            const float h = combine(d0 + p0, d1 + p1, d2 + p2, d3 + p3, cst0);
            puth(myrow, 24 + 8 * (t & 1), h);   // own h slot
            puth(myrow, 40 + 8 * (t & 1), h);   // L1 x slot
        }

        // ================= Layer 1: t = s-1 =================
        if ((unsigned)(s - 1) < (unsigned)Tn) {
            const int t = s - 1;
            const int xS = 40 + 8 * (t & 1);
            const int hS = 56 + 8 * ((t + 1) & 1);
            const uint4 xa = myrowq[xS], xb = myrowq[xS + 4];
            const uint4 ha = myrowq[hS], hb = myrowq[hS + 4];
            float d0 = bA1, d1 = bA1, d2 = bB1, d3 = bB1;
            float p0 = 0.f, p1 = 0.f, p2 = 0.f, p3 = 0.f;
            hmma(d0, d1, d2, d3, ax1[0][0], ax1[0][1], ax1[0][2], ax1[0][3], xa.x, xa.y);
            hmma(p0, p1, p2, p3, ax1[2][0], ax1[2][1], ax1[2][2], ax1[2][3], xb.x, xb.y);
            hmma(d0, d1, d2, d3, ax1[1][0], ax1[1][1], ax1[1][2], ax1[1][3], xa.z, xa.w);
            hmma(p0, p1, p2, p3, ax1[3][0], ax1[3][1], ax1[3][2], ax1[3][3], xb.z, xb.w);
            hmma(d0, d1, d2, d3, ah1[0][0], ah1[0][1], ah1[0][2], ah1[0][3], ha.x, ha.y);
            hmma(p0, p1, p2, p3, ah1[2][0], ah1[2][1], ah1[2][2], ah1[2][3], hb.x, hb.y);
            hmma(d0, d1, d2, d3, ah1[1][0], ah1[1][1], ah1[1][2], ah1[1][3], ha.z, ha.w);
            hmma(p0, p1, p2, p3, ah1[3][0], ah1[3][1], ah1[3][2], ah1[3][3], hb.z, hb.w);
            const float h = combine(d0 + p0, d1 + p1, d2 + p2, d3 + p3, cst1);
            puth(myrow, 56 + 8 * (t & 1), h);   // own h slot
            puth(myrow, 72 + 8 * (t & 1), h);   // L2 x slot
        }

        // ================= Layer 2: t = s-2 =================
        if ((unsigned)(s - 2) < (unsigned)Tn) {
            const int t = s - 2;
            const int xS = 72 + 8 * (t & 1);
            const int hS = 88 + 8 * ((t + 1) & 1);
            const uint4 xa = myrowq[xS], xb = myrowq[xS + 4];
            const uint4 ha = myrowq[hS], hb = myrowq[hS + 4];
            float d0 = bA2, d1 = bA2, d2 = bB2, d3 = bB2;
            float p0 = 0.f, p1 = 0.f, p2 = 0.f, p3 = 0.f;
            hmma(d0, d1, d2, d3, ax2[0][0], ax2[0][1], ax2[0][2], ax2[0][3], xa.x, xa.y);
            hmma(p0, p1, p2, p3, ax2[2][0], ax2[2][1], ax2[2][2], ax2[2][3], xb.x, xb.y);
            hmma(d0, d1, d2, d3, ax2[1][0], ax2[1][1], ax2[1][2], ax2[1][3], xa.z, xa.w);
            hmma(p0, p1, p2, p3, ax2[3][0], ax2[3][1], ax2[3][2], ax2[3][3], xb.z, xb.w);
            hmma(d0, d1, d2, d3, ah2[0][0], ah2[0][1], ah2[0][2], ah2[0][3], ha.x, ha.y);
            hmma(p0, p1, p2, p3, ah2[2][0], ah2[2][1], ah2[2][2], ah2[2][3], hb.x, hb.y);
            hmma(d0, d1, d2, d3, ah2[1][0], ah2[1][1], ah2[1][2], ah2[1][3], ha.z, ha.w);
            hmma(p0, p1, p2, p3, ah2[3][0], ah2[3][1], ah2[3][2], ah2[3][3], hb.z, hb.w);
            const float h = combine(d0 + p0, d1 + p1, d2 + p2, d3 + p3, cst2);
            puth(myrow, 88 + 8 * (t & 1), h);   // own h slot
            if (t == Tn - 1)
                h_s[myrow][cell] = h;           // final h for FC
        }

        // ---- L0 x staging: x(s+2) -> slot (s+2) mod 3 (loaded >=1 step ago) ----
        if (s + 2 < Tn)
            putx(8 * xsl_w, xna);
        xsl_w = (xsl_w == 2) ? 0 : xsl_w + 1;

        // shift prefetch pipeline
        xna = xnb;
        xnb = xnew;
    }

    __syncthreads();
    // final FC: out[b][o] = h_L2(T-1) . w_fc[o] + b_fc[o]
    if (tid < nrows * 4) {
        const int r = tid >> 2, o = tid & 3;
        float s = b_fc[o];
#pragma unroll
        for (int k = 0; k < Hn; k++)
            s += h_s[r][k] * w_fc[o * Hn + k];
        out_fc[(b0 + r) * 4 + o] = s;
    }
}

extern "C" void kernel_launch(void* const* d_in, const int* in_sizes, int n_in,
                              void* d_out, int out_size)
{
    const float* x    = (const float*)d_in[0];
    const float* wih0 = (const float*)d_in[1];
    const float* whh0 = (const float*)d_in[2];
    const float* bih0 = (const float*)d_in[3];
    const float* bhh0 = (const float*)d_in[4];
    const float* wih1 = (const float*)d_in[5];
    const float* whh1 = (const float*)d_in[6];
    const float* bih1 = (const float*)d_in[7];
    const float* bhh1 = (const float*)d_in[8];
    const float* wih2 = (const float*)d_in[9];
    const float* whh2 = (const float*)d_in[10];
    const float* bih2 = (const float*)d_in[11];
    const float* bhh2 = (const float*)d_in[12];
    const float* wfc  = (const float*)d_in[13];
    const float* bfc  = (const float*)d_in[14];
    float* out = (float*)d_out;

    transpose_x_k<<<Bn * 8, 256>>>(x);

    lstm3_k<<<GRID, NT>>>(wih0, whh0, bih0, bhh0,
                          wih1, whh1, bih1, bhh1,
                          wih2, whh2, bih2, bhh2,
                          wfc, bfc, out);
}

// round 17
// speedup vs baseline: 1.3750x; 1.3750x over previous
#include <cuda_runtime.h>
#include <cuda_fp16.h>
#include <cstdint>
#include <cstddef>

namespace {
constexpr int Bn   = 1024;
constexpr int BnP  = 1032;   // padded rows (zero tail)
constexpr int Tn   = 512;
constexpr int Hn   = 64;
constexpr int NB   = 7;      // real rows per block -> grid 147 (N=8 with pad row)
constexpr int GRID = 147;
constexpr int NT   = 512;    // 16 warps
constexpr int RQA  = 76;     // fused kernel bq row stride in uint4 (mod 8 = 4)
constexpr int RQB  = 36;     // L2 kernel bq row stride in uint4 (mod 8 = 4)
}

// L1 output sequence, [t][b][64] f32, rows >=1024 stay zero.
__device__ float g_seq1[(size_t)Tn * BnP * 64];
// Layer-0 input transposed+padded: [t][b][64] (cols 22..63 zero)
__device__ float g_x64[(size_t)Tn * BnP * 64];

__device__ __forceinline__ float htanh(float x) {   // HW MUFU.TANH
    float y;
    asm("tanh.approx.f32 %0, %1;" : "=f"(y) : "f"(x));
    return y;
}
__device__ __forceinline__ float sigm(float x) {    // 0.5 + 0.5*tanh(x/2)
    return fmaf(htanh(0.5f * x), 0.5f, 0.5f);
}
__device__ __forceinline__ uint32_t h2pk(float a, float b) {   // fp16x2 pack
    __half2 t = __floats2half2_rn(a, b);
    return *reinterpret_cast<uint32_t*>(&t);
}

// m16n8k16 fp16 MMA, fp32 accumulate (sm_80 baseline PTX).
__device__ __forceinline__ void hmma(float& d0, float& d1, float& d2, float& d3,
                                     uint32_t a0, uint32_t a1, uint32_t a2, uint32_t a3,
                                     uint32_t b0, uint32_t b1) {
    asm volatile(
        "mma.sync.aligned.m16n8k16.row.col.f32.f16.f16.f32 "
        "{%0,%1,%2,%3}, {%4,%5,%6,%7}, {%8,%9}, {%0,%1,%2,%3};"
        : "+f"(d0), "+f"(d1), "+f"(d2), "+f"(d3)
        : "r"(a0), "r"(a1), "r"(a2), "r"(a3), "r"(b0), "r"(b1));
}

// Transpose x[b][22][t] -> g_x64[t][b][0..63] (cols 22..63 zero).
__global__ void __launch_bounds__(256)
transpose_x_k(const float* __restrict__ x)
{
    const int b  = blockIdx.x >> 3;
    const int t0 = (blockIdx.x & 7) * 64;
    __shared__ float tile[22][65];
    for (int e = threadIdx.x; e < 22 * 64; e += 256) {
        int i = e / 64, tt = e - i * 64;
        tile[i][tt] = x[(size_t)b * (22 * Tn) + i * Tn + t0 + tt];
    }
    __syncthreads();
    for (int e = threadIdx.x; e < 64 * 64; e += 256) {
        int tt = e >> 6, i = e & 63;
        g_x64[((size_t)(t0 + tt) * BnP + b) * 64 + i] = (i < 22) ? tile[i][tt] : 0.f;
    }
}

// ============ Kernel 1: fused L0+L1, pipelined (L0 t=s, L1 t=s-1) ============
// Inter-layer h flows through the smem fragment tile. pure-fp16 HMMA,
// warp-local row-split combine, ONE __syncthreads per step.
// bq slots (uint4 base): L0 x triple @0/8/16; L0 h parity @24(+8);
//                        L1 x parity @40(+8);  L1 h parity @56(+8).
__global__ void __launch_bounds__(NT, 1)
lstm01_k(const float* __restrict__ wih0, const float* __restrict__ whh0,
         const float* __restrict__ bih0, const float* __restrict__ bhh0,
         const float* __restrict__ wih1, const float* __restrict__ whh1,
         const float* __restrict__ bih1, const float* __restrict__ bhh1)
{
    __shared__ __align__(16) uint4 bq[8][RQA];
    __shared__ float h_out[2][8][68];    // L1 h parity staging -> g_seq1

    const int tid  = threadIdx.x;
    const int lane = tid & 31;
    const int wrp  = tid >> 5;
    const int gid  = lane >> 2;
    const int qid  = lane & 3;
    const int b0   = blockIdx.x * NB;
    const int nrows = (Bn - b0 < NB) ? (Bn - b0) : NB;

    // permuted weight rows
    const int cell = 4 * wrp + (gid & 3);
    const int m0 = ((gid >> 2) ? 64 : 0)    + cell;
    const int m1 = ((gid >> 2) ? 192 : 128) + cell;

    // ---- fp16 weight fragments (2 layers), registers ----
    uint32_t ax0[2][4], ah0[4][4], ax1[4][4], ah1[4][4];
    {
        auto wx0 = [&](int m, int k) -> float {
            return (k < 22) ? wih0[m * 22 + k] : 0.f;
        };
#pragma unroll
        for (int kc = 0; kc < 2; kc++) {
            const int k0 = kc * 16 + qid * 2, k1 = k0 + 8;
            ax0[kc][0] = h2pk(wx0(m0, k0), wx0(m0, k0 + 1));
            ax0[kc][1] = h2pk(wx0(m1, k0), wx0(m1, k0 + 1));
            ax0[kc][2] = h2pk(wx0(m0, k1), wx0(m0, k1 + 1));
            ax0[kc][3] = h2pk(wx0(m1, k1), wx0(m1, k1 + 1));
        }
#pragma unroll
        for (int kc = 0; kc < 4; kc++) {
            const int k0 = kc * 16 + qid * 2, k1 = k0 + 8;
            ah0[kc][0] = h2pk(whh0[m0 * 64 + k0], whh0[m0 * 64 + k0 + 1]);
            ah0[kc][1] = h2pk(whh0[m1 * 64 + k0], whh0[m1 * 64 + k0 + 1]);
            ah0[kc][2] = h2pk(whh0[m0 * 64 + k1], whh0[m0 * 64 + k1 + 1]);
            ah0[kc][3] = h2pk(whh0[m1 * 64 + k1], whh0[m1 * 64 + k1 + 1]);
            ax1[kc][0] = h2pk(wih1[m0 * 64 + k0], wih1[m0 * 64 + k0 + 1]);
            ax1[kc][1] = h2pk(wih1[m1 * 64 + k0], wih1[m1 * 64 + k0 + 1]);
            ax1[kc][2] = h2pk(wih1[m0 * 64 + k1], wih1[m0 * 64 + k1 + 1]);
            ax1[kc][3] = h2pk(wih1[m1 * 64 + k1], wih1[m1 * 64 + k1 + 1]);
            ah1[kc][0] = h2pk(whh1[m0 * 64 + k0], whh1[m0 * 64 + k0 + 1]);
            ah1[kc][1] = h2pk(whh1[m1 * 64 + k0], whh1[m1 * 64 + k0 + 1]);
            ah1[kc][2] = h2pk(whh1[m0 * 64 + k1], whh1[m0 * 64 + k1 + 1]);
            ah1[kc][3] = h2pk(whh1[m1 * 64 + k1], whh1[m1 * 64 + k1 + 1]);
        }
    }
    const float bA0 = bih0[m0] + bhh0[m0], bB0 = bih0[m1] + bhh0[m1];
    const float bA1 = bih1[m0] + bhh1[m0], bB1 = bih1[m1] + bhh1[m1];

    const bool sideA = (lane < 16);
    const int  myrow = 2 * qid + (sideA ? 0 : 1);
    float cst0 = 0.f, cst1 = 0.f;

    const int sr = tid >> 6, sc = tid & 63;
    const int xw_u4   = (sc >> 5) * 4 + ((sc >> 1) & 3);
    const int xw_comp = (((sc >> 4) & 1) * 2 + ((sc >> 3) & 1)) * 2 + (sc & 1);
    const int hw_u4   = (cell >> 5) * 4 + ((cell >> 1) & 3);
    const int hw_comp = (((cell >> 4) & 1) * 2 + ((cell >> 3) & 1)) * 2 + (cell & 1);

    auto putx = [&](int S, float v) {
        reinterpret_cast<__half*>(&bq[sr][S + xw_u4])[xw_comp] = __float2half_rn(v);
    };
    auto puth = [&](int S, float v) {
        reinterpret_cast<__half*>(&bq[myrow][S + hw_u4])[hw_comp] = __float2half_rn(v);
    };
    auto ldx = [&](int t) -> float {
        return (t < Tn) ? g_x64[((size_t)t * BnP + b0 + sr) * 64 + sc] : 0.f;
    };
    auto combine = [&](float d0, float d1, float d2, float d3, float& cst) -> float {
        const float s1 = __shfl_xor_sync(0xffffffffu, sideA ? d1 : d0, 16);
        const float s2 = __shfl_xor_sync(0xffffffffu, sideA ? d3 : d2, 16);
        const float gi = sideA ? d0 : s1;
        const float gf = sideA ? s1 : d1;
        const float gg = sideA ? d2 : s2;
        const float go = sideA ? s2 : d3;
        const float iv = sigm(gi), fv = sigm(gf), gv = htanh(gg), ov = sigm(go);
        cst = fv * cst + iv * gv;
        return ov * htanh(cst);
    };

    for (int e = tid; e < 8 * RQA * 4; e += NT)
        reinterpret_cast<uint32_t*>(&bq[0][0])[e] = 0u;
    __syncthreads();
    putx(0, ldx(0));     // x(0) -> slot 0
    putx(8, ldx(1));     // x(1) -> slot 1
    __syncthreads();

    const uint4* myrowq = &bq[gid][qid];

    float xna = ldx(2);
    float xnb = ldx(3);
    int xsl_w = 2;       // (s+2) mod 3 at s=0

    for (int s = 0; s <= Tn; s++) {
        __syncthreads();

        float xnew = 0.f;
        if (s + 4 < Tn)
            xnew = g_x64[((size_t)(s + 4) * BnP + b0 + sr) * 64 + sc];

        // flush L1 h(s-2) to global (written at step s-1 into parity (s-2)&1 = s&1)
        if (s >= 2 && sr < nrows)
            g_seq1[((size_t)(s - 2) * BnP + b0 + sr) * 64 + sc] = h_out[s & 1][sr][sc];

        // ===== Layer 0: t = s =====
        if (s < Tn) {
            const int t = s;
            const int xS = 8 * (t - (t / 3) * 3);     // t mod 3
            const int hS = 24 + 8 * ((t + 1) & 1);
            const uint4 xa = myrowq[xS];
            const uint4 ha = myrowq[hS], hb = myrowq[hS + 4];
            float d0 = bA0, d1 = bA0, d2 = bB0, d3 = bB0;
            float p0 = 0.f, p1 = 0.f, p2 = 0.f, p3 = 0.f;
            hmma(d0, d1, d2, d3, ax0[0][0], ax0[0][1], ax0[0][2], ax0[0][3], xa.x, xa.y);
            hmma(p0, p1, p2, p3, ax0[1][0], ax0[1][1], ax0[1][2], ax0[1][3], xa.z, xa.w);
            hmma(d0, d1, d2, d3, ah0[0][0], ah0[0][1], ah0[0][2], ah0[0][3], ha.x, ha.y);
            hmma(p0, p1, p2, p3, ah0[2][0], ah0[2][1], ah0[2][2], ah0[2][3], hb.x, hb.y);
            hmma(d0, d1, d2, d3, ah0[1][0], ah0[1][1], ah0[1][2], ah0[1][3], ha.z, ha.w);
            hmma(p0, p1, p2, p3, ah0[3][0], ah0[3][1], ah0[3][2], ah0[3][3], hb.z, hb.w);
            const float h = combine(d0 + p0, d1 + p1, d2 + p2, d3 + p3, cst0);
            puth(24 + 8 * (t & 1), h);   // own h slot
            puth(40 + 8 * (t & 1), h);   // L1 x slot
        }

        // ===== Layer 1: t = s-1 =====
        if ((unsigned)(s - 1) < (unsigned)Tn) {
            const int t = s - 1;
            const int xS = 40 + 8 * (t & 1);
            const int hS = 56 + 8 * ((t + 1) & 1);
            const uint4 xa = myrowq[xS], xb = myrowq[xS + 4];
            const uint4 ha = myrowq[hS], hb = myrowq[hS + 4];
            float d0 = bA1, d1 = bA1, d2 = bB1, d3 = bB1;
            float p0 = 0.f, p1 = 0.f, p2 = 0.f, p3 = 0.f;
            hmma(d0, d1, d2, d3, ax1[0][0], ax1[0][1], ax1[0][2], ax1[0][3], xa.x, xa.y);
            hmma(p0, p1, p2, p3, ax1[2][0], ax1[2][1], ax1[2][2], ax1[2][3], xb.x, xb.y);
            hmma(d0, d1, d2, d3, ax1[1][0], ax1[1][1], ax1[1][2], ax1[1][3], xa.z, xa.w);
            hmma(p0, p1, p2, p3, ax1[3][0], ax1[3][1], ax1[3][2], ax1[3][3], xb.z, xb.w);
            hmma(d0, d1, d2, d3, ah1[0][0], ah1[0][1], ah1[0][2], ah1[0][3], ha.x, ha.y);
            hmma(p0, p1, p2, p3, ah1[2][0], ah1[2][1], ah1[2][2], ah1[2][3], hb.x, hb.y);
            hmma(d0, d1, d2, d3, ah1[1][0], ah1[1][1], ah1[1][2], ah1[1][3], ha.z, ha.w);
            hmma(p0, p1, p2, p3, ah1[3][0], ah1[3][1], ah1[3][2], ah1[3][3], hb.z, hb.w);
            const float h = combine(d0 + p0, d1 + p1, d2 + p2, d3 + p3, cst1);
            puth(56 + 8 * (t & 1), h);        // own h slot
            h_out[t & 1][myrow][cell] = h;    // staging -> g_seq1
        }

        // L0 x staging: x(s+2) -> slot (s+2) mod 3 (loaded >=1 step ago)
        if (s + 2 < Tn)
            putx(8 * xsl_w, xna);
        xsl_w = (xsl_w == 2) ? 0 : xsl_w + 1;

        xna = xnb;
        xnb = xnew;
    }

    __syncthreads();
    // final flush: L1 h(Tn-1), written at step Tn into parity (Tn-1)&1
    if (sr < nrows)
        g_seq1[((size_t)(Tn - 1) * BnP + b0 + sr) * 64 + sc] =
            h_out[(Tn - 1) & 1][sr][sc];
}

// ============ Kernel 2: L2 standalone (R15 structure) + final FC ============
__global__ void __launch_bounds__(NT, 1)
lstm2_k(const float* __restrict__ w_ih, const float* __restrict__ w_hh,
        const float* __restrict__ b_ih, const float* __restrict__ b_hh,
        const float* __restrict__ w_fc, const float* __restrict__ b_fc,
        float* __restrict__ out_fc)
{
    const float* xin = g_seq1;

    __shared__ __align__(16) uint4 bq[8][RQB];
    __shared__ float h_s[8][64];

    const int tid  = threadIdx.x;
    const int lane = tid & 31;
    const int wrp  = tid >> 5;
    const int gid  = lane >> 2;
    const int qid  = lane & 3;
    const int b0   = blockIdx.x * NB;
    const int nrows = (Bn - b0 < NB) ? (Bn - b0) : NB;

    const int cell = 4 * wrp + (gid & 3);
    const int m0 = ((gid >> 2) ? 64 : 0)    + cell;
    const int m1 = ((gid >> 2) ? 192 : 128) + cell;

    uint32_t axh[4][4], ahh[4][4];
#pragma unroll
    for (int kc = 0; kc < 4; kc++) {
        const int k0 = kc * 16 + qid * 2, k1 = k0 + 8;
        axh[kc][0] = h2pk(w_ih[m0 * 64 + k0], w_ih[m0 * 64 + k0 + 1]);
        axh[kc][1] = h2pk(w_ih[m1 * 64 + k0], w_ih[m1 * 64 + k0 + 1]);
        axh[kc][2] = h2pk(w_ih[m0 * 64 + k1], w_ih[m0 * 64 + k1 + 1]);
        axh[kc][3] = h2pk(w_ih[m1 * 64 + k1], w_ih[m1 * 64 + k1 + 1]);
        ahh[kc][0] = h2pk(w_hh[m0 * 64 + k0], w_hh[m0 * 64 + k0 + 1]);
        ahh[kc][1] = h2pk(w_hh[m1 * 64 + k0], w_hh[m1 * 64 + k0 + 1]);
        ahh[kc][2] = h2pk(w_hh[m0 * 64 + k1], w_hh[m0 * 64 + k1 + 1]);
        ahh[kc][3] = h2pk(w_hh[m1 * 64 + k1], w_hh[m1 * 64 + k1 + 1]);
    }
    const float biasA = b_ih[m0] + b_hh[m0];
    const float biasB = b_ih[m1] + b_hh[m1];

    const bool sideA = (lane < 16);
    const int  myrow = 2 * qid + (sideA ? 0 : 1);
    float cst = 0.f;

    const int sr = tid >> 6, sc = tid & 63;
    const int xw_u4   = (sc >> 5) * 4 + ((sc >> 1) & 3);
    const int xw_comp = (((sc >> 4) & 1) * 2 + ((sc >> 3) & 1)) * 2 + (sc & 1);
    const int hw_u4   = (cell >> 5) * 4 + ((cell >> 1) & 3);
    const int hw_comp = (((cell >> 4) & 1) * 2 + ((cell >> 3) & 1)) * 2 + (cell & 1);

    auto putx = [&](int S, float v) {
        reinterpret_cast<__half*>(&bq[sr][S + xw_u4])[xw_comp] = __float2half_rn(v);
    };
    auto ldx = [&](int t) -> float {
        return (t < Tn) ? xin[((size_t)t * BnP + b0 + sr) * 64 + sc] : 0.f;
    };

    for (int e = tid; e < 8 * RQB * 4; e += NT)
        reinterpret_cast<uint32_t*>(&bq[0][0])[e] = 0u;
    __syncthreads();
    putx(0, ldx(0));
    putx(8, ldx(1));
    __syncthreads();

    const uint4* myrowq = &bq[gid][qid];

    float cx0, cx1, cx2, cx3;
    auto xproj = [&](int slot) {
        float d0 = biasA, d1 = biasA, d2 = biasB, d3 = biasB;
        const int S = 8 * slot;
        const uint4 va = myrowq[S];
        const uint4 vb = myrowq[S + 4];
        hmma(d0, d1, d2, d3, axh[0][0], axh[0][1], axh[0][2], axh[0][3], va.x, va.y);
        hmma(d0, d1, d2, d3, axh[1][0], axh[1][1], axh[1][2], axh[1][3], va.z, va.w);
        hmma(d0, d1, d2, d3, axh[2][0], axh[2][1], axh[2][2], axh[2][3], vb.x, vb.y);
        hmma(d0, d1, d2, d3, axh[3][0], axh[3][1], axh[3][2], axh[3][3], vb.z, vb.w);
        cx0 = d0; cx1 = d1; cx2 = d2; cx3 = d3;
    };

    xproj(0);

    float xna = ldx(2);
    float xnb = ldx(3);

    for (int t = 0; t < Tn; t++) {
        __syncthreads();

        float xnew = 0.f;
        if (t + 4 < Tn)
            xnew = xin[((size_t)(t + 4) * BnP + b0 + sr) * 64 + sc];

        float d0 = cx0, d1 = cx1, d2 = cx2, d3 = cx3;
        float p0 = 0.f, p1 = 0.f, p2 = 0.f, p3 = 0.f;
        const int hS = 16 + 8 * ((t + 1) & 1);
        {
            const uint4 va = myrowq[hS];
            const uint4 vb = myrowq[hS + 4];
            hmma(d0, d1, d2, d3, ahh[0][0], ahh[0][1], ahh[0][2], ahh[0][3], va.x, va.y);
            hmma(p0, p1, p2, p3, ahh[2][0], ahh[2][1], ahh[2][2], ahh[2][3], vb.x, vb.y);
            hmma(d0, d1, d2, d3, ahh[1][0], ahh[1][1], ahh[1][2], ahh[1][3], va.z, va.w);
            hmma(p0, p1, p2, p3, ahh[3][0], ahh[3][1], ahh[3][2], ahh[3][3], vb.z, vb.w);
        }
        d0 += p0; d1 += p1; d2 += p2; d3 += p3;

        if (t + 1 < Tn) xproj((t + 1) & 1);

        const float s1 = __shfl_xor_sync(0xffffffffu, sideA ? d1 : d0, 16);
        const float s2 = __shfl_xor_sync(0xffffffffu, sideA ? d3 : d2, 16);
        const float gi = sideA ? d0 : s1;
        const float gf = sideA ? s1 : d1;
        const float gg = sideA ? d2 : s2;
        const float go = sideA ? s2 : d3;

        const float iv = sigm(gi), fv = sigm(gf), gv = htanh(gg), ov = sigm(go);
        cst = fv * cst + iv * gv;
        const float h = ov * htanh(cst);

        {
            const int hw = 16 + 8 * (t & 1);
            reinterpret_cast<__half*>(&bq[myrow][hw + hw_u4])[hw_comp] = __float2half_rn(h);
            if (t == Tn - 1)
                h_s[myrow][cell] = h;
        }
        if (t + 2 < Tn)
            putx(8 * (t & 1), xna);

        xna = xnb;
        xnb = xnew;
    }

    __syncthreads();
    if (tid < nrows * 4) {
        const int r = tid >> 2, o = tid & 3;
        float s = b_fc[o];
#pragma unroll
        for (int k = 0; k < Hn; k++)
            s += h_s[r][k] * w_fc[o * Hn + k];
        out_fc[(b0 + r) * 4 + o] = s;
    }
}

extern "C" void kernel_launch(void* const* d_in, const int* in_sizes, int n_in,
                              void* d_out, int out_size)
{
    const float* x    = (const float*)d_in[0];
    const float* wih0 = (const float*)d_in[1];
    const float* whh0 = (const float*)d_in[2];
    const float* bih0 = (const float*)d_in[3];
    const float* bhh0 = (const float*)d_in[4];
    const float* wih1 = (const float*)d_in[5];
    const float* whh1 = (const float*)d_in[6];
    const float* bih1 = (const float*)d_in[7];
    const float* bhh1 = (const float*)d_in[8];
    const float* wih2 = (const float*)d_in[9];
    const float* whh2 = (const float*)d_in[10];
    const float* bih2 = (const float*)d_in[11];
    const float* bhh2 = (const float*)d_in[12];
    const float* wfc  = (const float*)d_in[13];
    const float* bfc  = (const float*)d_in[14];
    float* out = (float*)d_out;

    transpose_x_k<<<Bn * 8, 256>>>(x);

    lstm01_k<<<GRID, NT>>>(wih0, whh0, bih0, bhh0, wih1, whh1, bih1, bhh1);
    lstm2_k<<<GRID, NT>>>(wih2, whh2, bih2, bhh2, wfc, bfc, out);
}